// round 11
// baseline (speedup 1.0000x reference)
#include <cuda_runtime.h>
#include <cuda_fp16.h>
#include <math.h>

#define N_NODES 100000
#define IN_DIM 64
#define HALF 32

// ---------------- scratch (device globals: allocation-free) ----------------
__device__ __half g_xT[N_NODES * 64];     // fp16 [x@W1b_agg | x@W1u_agg]  12.8MB
__device__ float4 g_agg1P[N_NODES * 8];   // f32 32-dim agg over pos
__device__ float4 g_agg1N[N_NODES * 8];   // f32 32-dim agg over neg
__device__ float4 g_z[N_NODES * 16];      // layer-1 output, f32
__device__ __half g_zT[N_NODES * 128];    // fp16 [u | v]  25.6MB
__device__ float4 g_agg2P[N_NODES * 16];  // f32 64-dim agg over pos
__device__ float4 g_agg2N[N_NODES * 16];  // f32 64-dim agg over neg
__device__ float  g_cntP[N_NODES];
__device__ float  g_cntN[N_NODES];

__device__ __forceinline__ float ftanh(float v) {
    float e = __expf(2.0f * v);
    return 1.0f - 2.0f / (e + 1.0f);
}

// ---------------- zero kernels ----------------
__global__ void __launch_bounds__(256) zero1() {
    int i = blockIdx.x * blockDim.x + threadIdx.x;
    float4 z4 = make_float4(0.f, 0.f, 0.f, 0.f);
    if (i < N_NODES * 8) { g_agg1P[i] = z4; g_agg1N[i] = z4; }
    if (i < N_NODES)     { g_cntP[i] = 0.f; g_cntN[i] = 0.f; }
}
__global__ void __launch_bounds__(256) zero2() {
    int i = blockIdx.x * blockDim.x + threadIdx.x;
    float4 z4 = make_float4(0.f, 0.f, 0.f, 0.f);
    if (i < N_NODES * 16) { g_agg2P[i] = z4; g_agg2N[i] = z4; }
}

// ---------------- layer-1 aggregation: fp16 gather, f32 red ----------------
// 4 threads/edge, each 8 halfs (16B). pos: xT cols 0:32, neg: 32:64.
__global__ void __launch_bounds__(256)
agg1_kernel(const int* __restrict__ src, const int* __restrict__ dst, int E, int isNeg)
{
    int t = blockIdx.x * blockDim.x + threadIdx.x;
    if (t >= E * 4) return;
    int e = t >> 2, c = t & 3;
    int s = __ldg(src + e);
    int d = __ldg(dst + e);
    uint4 pv = __ldg((const uint4*)(g_xT + s * 64 + isNeg * 32) + c);
    float2 f0 = __half22float2(*(const __half2*)&pv.x);
    float2 f1 = __half22float2(*(const __half2*)&pv.y);
    float2 f2 = __half22float2(*(const __half2*)&pv.z);
    float2 f3 = __half22float2(*(const __half2*)&pv.w);
    float* p = (float*)((isNeg ? g_agg1N : g_agg1P) + d * 8) + c * 8;
    asm volatile("red.global.add.v4.f32 [%0], {%1,%2,%3,%4};"
                 :: "l"(p), "f"(f0.x), "f"(f0.y), "f"(f1.x), "f"(f1.y) : "memory");
    asm volatile("red.global.add.v4.f32 [%0], {%1,%2,%3,%4};"
                 :: "l"(p + 4), "f"(f2.x), "f"(f2.y), "f"(f3.x), "f"(f3.y) : "memory");
    if (c == 0) atomicAdd((isNeg ? g_cntN : g_cntP) + d, 1.0f);
}

// ---------------- layer-2 aggregation: fp16 gather, f32 red ----------------
// 8 threads/edge. pos: zT cols 0:64 (u), neg: 64:128 (v).
__global__ void __launch_bounds__(256)
agg2_kernel(const int* __restrict__ src, const int* __restrict__ dst, int E, int isNeg)
{
    int t = blockIdx.x * blockDim.x + threadIdx.x;
    if (t >= E * 8) return;
    int e = t >> 3, c = t & 7;
    int s = __ldg(src + e);
    int d = __ldg(dst + e);
    uint4 pv = __ldg((const uint4*)(g_zT + s * 128 + isNeg * 64) + c);
    float2 f0 = __half22float2(*(const __half2*)&pv.x);
    float2 f1 = __half22float2(*(const __half2*)&pv.y);
    float2 f2 = __half22float2(*(const __half2*)&pv.z);
    float2 f3 = __half22float2(*(const __half2*)&pv.w);
    float* p = (float*)((isNeg ? g_agg2N : g_agg2P) + d * 16) + c * 8;
    asm volatile("red.global.add.v4.f32 [%0], {%1,%2,%3,%4};"
                 :: "l"(p), "f"(f0.x), "f"(f0.y), "f"(f1.x), "f"(f1.y) : "memory");
    asm volatile("red.global.add.v4.f32 [%0], {%1,%2,%3,%4};"
                 :: "l"(p + 4), "f"(f2.x), "f"(f2.y), "f"(f3.x), "f"(f3.y) : "memory");
}

// ---------------- transform1: xT = [x@w1b(rows 0:64) | x@w1u(rows 0:64)] (fp16 out) ----------------
#define KS1 68
__global__ void __launch_bounds__(256, 4)
transform1_kernel(const float* __restrict__ x,
                  const float* __restrict__ w1b, const float* __restrict__ w1u)
{
    __shared__ float sW[2][32][KS1];
    int tid = threadIdx.x;
    for (int i = tid; i < 64 * 32; i += 256) {
        int k = i >> 5, j = i & 31;
        sW[0][j][k] = w1b[i];
        sW[1][j][k] = w1u[i];
    }
    __syncthreads();

    int jg = tid & 15, ng = tid >> 4;
    int branch = jg >> 3, jb = jg & 7;
    int nbase = blockIdx.x * 64 + ng * 4;
    int nidx[4];
    #pragma unroll
    for (int ni = 0; ni < 4; ni++) {
        int n = nbase + ni; if (n > N_NODES - 1) n = N_NODES - 1;
        nidx[ni] = n;
    }

    float acc[4][4];
    #pragma unroll
    for (int ni = 0; ni < 4; ni++)
        #pragma unroll
        for (int o = 0; o < 4; o++) acc[ni][o] = 0.f;

    #pragma unroll 4
    for (int ch = 0; ch < 16; ch++) {
        float4 v[4], w[4];
        #pragma unroll
        for (int ni = 0; ni < 4; ni++)
            v[ni] = __ldg((const float4*)(x + nidx[ni] * 64 + ch * 4));
        #pragma unroll
        for (int o = 0; o < 4; o++)
            w[o] = *(const float4*)&sW[branch][jb + 8 * o][ch * 4];
        #pragma unroll
        for (int ni = 0; ni < 4; ni++)
            #pragma unroll
            for (int o = 0; o < 4; o++) {
                acc[ni][o] = fmaf(v[ni].x, w[o].x, acc[ni][o]);
                acc[ni][o] = fmaf(v[ni].y, w[o].y, acc[ni][o]);
                acc[ni][o] = fmaf(v[ni].z, w[o].z, acc[ni][o]);
                acc[ni][o] = fmaf(v[ni].w, w[o].w, acc[ni][o]);
            }
    }

    #pragma unroll
    for (int ni = 0; ni < 4; ni++) {
        int n = nbase + ni;
        if (n < N_NODES) {
            #pragma unroll
            for (int o = 0; o < 4; o++)
                g_xT[n * 64 + branch * 32 + jb + 8 * o] = __float2half_rn(acc[ni][o]);
        }
    }
}

// ---------------- linear1: z = tanh(agg1*inv + x@Wself + b) ----------------
__global__ void __launch_bounds__(256, 4)
linear1_lite(const float* __restrict__ x,
             const float* __restrict__ w1b, const float* __restrict__ b1b,
             const float* __restrict__ w1u, const float* __restrict__ b1u)
{
    __shared__ float sW[2][32][KS1];   // self rows 64:127
    __shared__ float sB[64];
    int tid = threadIdx.x;
    for (int i = tid; i < 64 * 32; i += 256) {
        int k = i >> 5, j = i & 31;
        sW[0][j][k] = w1b[2048 + i];
        sW[1][j][k] = w1u[2048 + i];
    }
    if (tid < 32) { sB[tid] = b1b[tid]; sB[tid + 32] = b1u[tid]; }
    __syncthreads();

    int jg = tid & 15, ng = tid >> 4;
    int branch = jg >> 3, jb = jg & 7;
    int nbase = blockIdx.x * 64 + ng * 4;
    int nidx[4];
    #pragma unroll
    for (int ni = 0; ni < 4; ni++) {
        int n = nbase + ni; if (n > N_NODES - 1) n = N_NODES - 1;
        nidx[ni] = n;
    }

    float acc[4][4];
    #pragma unroll
    for (int ni = 0; ni < 4; ni++)
        #pragma unroll
        for (int o = 0; o < 4; o++)
            acc[ni][o] = sB[branch * 32 + jb + 8 * o];

    #pragma unroll 4
    for (int ch = 0; ch < 16; ch++) {
        float4 v[4], w[4];
        #pragma unroll
        for (int ni = 0; ni < 4; ni++)
            v[ni] = __ldg((const float4*)(x + nidx[ni] * 64 + ch * 4));
        #pragma unroll
        for (int o = 0; o < 4; o++)
            w[o] = *(const float4*)&sW[branch][jb + 8 * o][ch * 4];
        #pragma unroll
        for (int ni = 0; ni < 4; ni++)
            #pragma unroll
            for (int o = 0; o < 4; o++) {
                acc[ni][o] = fmaf(v[ni].x, w[o].x, acc[ni][o]);
                acc[ni][o] = fmaf(v[ni].y, w[o].y, acc[ni][o]);
                acc[ni][o] = fmaf(v[ni].z, w[o].z, acc[ni][o]);
                acc[ni][o] = fmaf(v[ni].w, w[o].w, acc[ni][o]);
            }
    }

    const float* agg = branch ? (const float*)g_agg1N : (const float*)g_agg1P;
    const float* cnt = branch ? g_cntN : g_cntP;
    float* zout = (float*)g_z;
    #pragma unroll
    for (int ni = 0; ni < 4; ni++) {
        int n = nbase + ni;
        if (n < N_NODES) {
            float inv = 1.0f / fmaxf(cnt[n], 1.0f);
            #pragma unroll
            for (int o = 0; o < 4; o++) {
                float a = __ldg(agg + n * 32 + jb + 8 * o);
                zout[n * 64 + branch * 32 + jb + 8 * o] = ftanh(acc[ni][o] + a * inv);
            }
        }
    }
}

// ---------------- transform2: zT = [u | v] (fp16 out) ----------------
// u[0:32]=zp@w2b[0:32]   u[32:64]=zn@w2u[0:32]
// v[0:32]=zn@w2b[32:64]  v[32:64]=zp@w2u[32:64]
__global__ void __launch_bounds__(256, 4)
transform2_kernel(const float* __restrict__ w2b, const float* __restrict__ w2u)
{
    __shared__ float sW[2][32][KS1];   // w2b/w2u rows 0:64
    int tid = threadIdx.x;
    for (int i = tid; i < 64 * 32; i += 256) {
        int k = i >> 5, j = i & 31;
        sW[0][j][k] = w2b[i];
        sW[1][j][k] = w2u[i];
    }
    __syncthreads();

    int jg = tid & 31, ng = tid >> 5;
    int q = jg >> 3, jb = jg & 7;
    int h  = (q == 1 || q == 2) ? 1 : 0;
    int wb = (q == 0 || q == 2) ? 0 : 1;
    int ro = (q >= 2) ? 32 : 0;
    int nbase = blockIdx.x * 32 + ng * 4;
    int nidx[4];
    #pragma unroll
    for (int ni = 0; ni < 4; ni++) {
        int n = nbase + ni; if (n > N_NODES - 1) n = N_NODES - 1;
        nidx[ni] = n;
    }

    const float* z = (const float*)g_z;
    float acc[4][4];
    #pragma unroll
    for (int ni = 0; ni < 4; ni++)
        #pragma unroll
        for (int o = 0; o < 4; o++) acc[ni][o] = 0.f;

    #pragma unroll
    for (int ch = 0; ch < 8; ch++) {
        float4 v[4], w[4];
        #pragma unroll
        for (int ni = 0; ni < 4; ni++)
            v[ni] = __ldg((const float4*)(z + nidx[ni] * 64 + h * 32 + ch * 4));
        #pragma unroll
        for (int o = 0; o < 4; o++)
            w[o] = *(const float4*)&sW[wb][jb + 8 * o][ro + ch * 4];
        #pragma unroll
        for (int ni = 0; ni < 4; ni++)
            #pragma unroll
            for (int o = 0; o < 4; o++) {
                acc[ni][o] = fmaf(v[ni].x, w[o].x, acc[ni][o]);
                acc[ni][o] = fmaf(v[ni].y, w[o].y, acc[ni][o]);
                acc[ni][o] = fmaf(v[ni].z, w[o].z, acc[ni][o]);
                acc[ni][o] = fmaf(v[ni].w, w[o].w, acc[ni][o]);
            }
    }

    #pragma unroll
    for (int ni = 0; ni < 4; ni++) {
        int n = nbase + ni;
        if (n < N_NODES) {
            #pragma unroll
            for (int o = 0; o < 4; o++)
                g_zT[n * 128 + q * 32 + jb + 8 * o] = __float2half_rn(acc[ni][o]);
        }
    }
}

// ---------------- linear2: out = tanh(agg2P*invP + agg2N*invN + z_self@Wself + b) ----------------
#define KS2 36
__global__ void __launch_bounds__(256, 4)
linear2_lite(const float* __restrict__ w2b, const float* __restrict__ b2b,
             const float* __restrict__ w2u, const float* __restrict__ b2u,
             float* __restrict__ out)
{
    __shared__ float sW[2][32][KS2];   // self rows 64:95
    __shared__ float sB[64];
    int tid = threadIdx.x;
    for (int i = tid; i < 32 * 32; i += 256) {
        int k = i >> 5, j = i & 31;
        sW[0][j][k] = w2b[2048 + i];
        sW[1][j][k] = w2u[2048 + i];
    }
    if (tid < 32) { sB[tid] = b2b[tid]; sB[tid + 32] = b2u[tid]; }
    __syncthreads();

    int jg = tid & 15, ng = tid >> 4;
    int branch = jg >> 3, jb = jg & 7;
    int nbase = blockIdx.x * 64 + ng * 4;
    int nidx[4];
    #pragma unroll
    for (int ni = 0; ni < 4; ni++) {
        int n = nbase + ni; if (n > N_NODES - 1) n = N_NODES - 1;
        nidx[ni] = n;
    }

    const float* z = (const float*)g_z;
    float acc[4][4];
    #pragma unroll
    for (int ni = 0; ni < 4; ni++)
        #pragma unroll
        for (int o = 0; o < 4; o++)
            acc[ni][o] = sB[branch * 32 + jb + 8 * o];

    #pragma unroll
    for (int ch = 0; ch < 8; ch++) {
        float4 v[4], w[4];
        #pragma unroll
        for (int ni = 0; ni < 4; ni++)
            v[ni] = __ldg((const float4*)(z + nidx[ni] * 64 + branch * 32 + ch * 4));
        #pragma unroll
        for (int o = 0; o < 4; o++)
            w[o] = *(const float4*)&sW[branch][jb + 8 * o][ch * 4];
        #pragma unroll
        for (int ni = 0; ni < 4; ni++)
            #pragma unroll
            for (int o = 0; o < 4; o++) {
                acc[ni][o] = fmaf(v[ni].x, w[o].x, acc[ni][o]);
                acc[ni][o] = fmaf(v[ni].y, w[o].y, acc[ni][o]);
                acc[ni][o] = fmaf(v[ni].z, w[o].z, acc[ni][o]);
                acc[ni][o] = fmaf(v[ni].w, w[o].w, acc[ni][o]);
            }
    }

    const float* aU = (const float*)g_agg2P;
    const float* aV = (const float*)g_agg2N;
    #pragma unroll
    for (int ni = 0; ni < 4; ni++) {
        int n = nbase + ni;
        if (n < N_NODES) {
            float invP = 1.0f / fmaxf(g_cntP[n], 1.0f);
            float invN = 1.0f / fmaxf(g_cntN[n], 1.0f);
            #pragma unroll
            for (int o = 0; o < 4; o++) {
                int j = branch * 32 + jb + 8 * o;
                float au = __ldg(aU + n * 64 + j);
                float av = __ldg(aV + n * 64 + j);
                out[n * 64 + j] = ftanh(acc[ni][o] + au * invP + av * invN);
            }
        }
    }
}

// ---------------- launch ----------------
extern "C" void kernel_launch(void* const* d_in, const int* in_sizes, int n_in,
                              void* d_out, int out_size)
{
    const float* x    = (const float*)d_in[0];
    const int* posEI  = (const int*)d_in[1];
    const int* negEI  = (const int*)d_in[2];
    const float* w1b  = (const float*)d_in[3];
    const float* b1b  = (const float*)d_in[4];
    const float* w1u  = (const float*)d_in[5];
    const float* b1u  = (const float*)d_in[6];
    const float* w2b  = (const float*)d_in[7];
    const float* b2b  = (const float*)d_in[8];
    const float* w2u  = (const float*)d_in[9];
    const float* b2u  = (const float*)d_in[10];
    float* out = (float*)d_out;

    int E = in_sizes[1] / 2;             // 1,600,000
    const int* posSrc = posEI;
    const int* posDst = posEI + E;
    const int* negSrc = negEI;
    const int* negDst = negEI + E;

    int zero1Grid = (N_NODES * 8 + 255) / 256;
    int zero2Grid = (N_NODES * 16 + 255) / 256;
    int agg1Grid  = (E * 4 + 255) / 256;    // 25,000
    int agg2Grid  = (E * 8 + 255) / 256;    // 50,000
    int lin64Grid = (N_NODES + 63) / 64;    // 1563
    int lin32Grid = (N_NODES + 31) / 32;    // 3125

    // --- layer 1 ---
    zero1<<<zero1Grid, 256>>>();
    transform1_kernel<<<lin64Grid, 256>>>(x, w1b, w1u);
    agg1_kernel<<<agg1Grid, 256>>>(posSrc, posDst, E, 0);
    agg1_kernel<<<agg1Grid, 256>>>(negSrc, negDst, E, 1);
    linear1_lite<<<lin64Grid, 256>>>(x, w1b, b1b, w1u, b1u);

    // --- layer 2 ---
    zero2<<<zero2Grid, 256>>>();
    transform2_kernel<<<lin32Grid, 256>>>(w2b, w2u);
    agg2_kernel<<<agg2Grid, 256>>>(posSrc, posDst, E, 0);
    agg2_kernel<<<agg2Grid, 256>>>(negSrc, negDst, E, 1);
    linear2_lite<<<lin64Grid, 256>>>(w2b, b2b, w2u, b2u, out);
}

// round 13
// speedup vs baseline: 1.1024x; 1.1024x over previous
#include <cuda_runtime.h>
#include <cuda_fp16.h>
#include <math.h>

#define N_NODES 100000
#define IN_DIM 64
#define HALF 32

// ---------------- scratch (device globals: allocation-free) ----------------
__device__ __half g_xT[N_NODES * 64];     // fp16 [x@W1b_agg | x@W1u_agg]
__device__ float4 g_agg1P[N_NODES * 8];   // f32 32-dim agg over pos
__device__ float4 g_agg1N[N_NODES * 8];   // f32 32-dim agg over neg
__device__ float4 g_z[N_NODES * 16];      // layer-1 output, f32
__device__ __half g_zT[N_NODES * 128];    // fp16 [u | v]
__device__ float4 g_agg2P[N_NODES * 16];  // f32 64-dim agg over pos
__device__ float4 g_agg2N[N_NODES * 16];  // f32 64-dim agg over neg
__device__ float  g_cntP[N_NODES];
__device__ float  g_cntN[N_NODES];

__device__ __forceinline__ float ftanh(float v) {
    float e = __expf(2.0f * v);
    return 1.0f - 2.0f / (e + 1.0f);
}

// ---------------- layer-1 aggregation: merged pos+neg, fp16 8B gather, one f32 red.v4/thread ----------------
__global__ void __launch_bounds__(256)
agg1_kernel(const int* __restrict__ posSrc, const int* __restrict__ posDst,
            const int* __restrict__ negSrc, const int* __restrict__ negDst, int E)
{
    int t = blockIdx.x * blockDim.x + threadIdx.x;
    if (t >= E * 16) return;
    int isNeg = (t >= E * 8);
    int tt = isNeg ? t - E * 8 : t;
    int e = tt >> 3, c = tt & 7;
    const int* src = isNeg ? negSrc : posSrc;
    const int* dst = isNeg ? negDst : posDst;
    int s = __ldg(src + e);
    int d = __ldg(dst + e);
    uint2 pv = __ldg((const uint2*)(g_xT + s * 64 + isNeg * 32) + c);
    float2 f0 = __half22float2(*(const __half2*)&pv.x);
    float2 f1 = __half22float2(*(const __half2*)&pv.y);
    float* p = (float*)(isNeg ? g_agg1N : g_agg1P) + d * 32 + c * 4;
    asm volatile("red.global.add.v4.f32 [%0], {%1,%2,%3,%4};"
                 :: "l"(p), "f"(f0.x), "f"(f0.y), "f"(f1.x), "f"(f1.y) : "memory");
    if (c == 0) atomicAdd((isNeg ? g_cntN : g_cntP) + d, 1.0f);
}

// ---------------- layer-2 aggregation: merged pos+neg, fp16 8B gather, one f32 red.v4/thread ----------------
__global__ void __launch_bounds__(256)
agg2_kernel(const int* __restrict__ posSrc, const int* __restrict__ posDst,
            const int* __restrict__ negSrc, const int* __restrict__ negDst, int E)
{
    int t = blockIdx.x * blockDim.x + threadIdx.x;
    if (t >= E * 32) return;
    int isNeg = (t >= E * 16);
    int tt = isNeg ? t - E * 16 : t;
    int e = tt >> 4, c = tt & 15;
    const int* src = isNeg ? negSrc : posSrc;
    const int* dst = isNeg ? negDst : posDst;
    int s = __ldg(src + e);
    int d = __ldg(dst + e);
    uint2 pv = __ldg((const uint2*)(g_zT + s * 128 + isNeg * 64) + c);
    float2 f0 = __half22float2(*(const __half2*)&pv.x);
    float2 f1 = __half22float2(*(const __half2*)&pv.y);
    float* p = (float*)(isNeg ? g_agg2N : g_agg2P) + d * 64 + c * 4;
    asm volatile("red.global.add.v4.f32 [%0], {%1,%2,%3,%4};"
                 :: "l"(p), "f"(f0.x), "f"(f0.y), "f"(f1.x), "f"(f1.y) : "memory");
}

// ---------------- transform1: xT = [x@w1b(rows 0:64) | x@w1u(rows 0:64)] (fp16 out) + zero agg1 ----------------
#define KS1 68
__global__ void __launch_bounds__(256, 4)
transform1_kernel(const float* __restrict__ x,
                  const float* __restrict__ w1b, const float* __restrict__ w1u)
{
    __shared__ float sW[2][32][KS1];
    int tid = threadIdx.x;
    for (int i = tid; i < 64 * 32; i += 256) {
        int k = i >> 5, j = i & 31;
        sW[0][j][k] = w1b[i];
        sW[1][j][k] = w1u[i];
    }

    // zero this block's agg1 rows + counts (64 nodes x 8 float4 per buffer)
    int nbase0 = blockIdx.x * 64;
    float4 z4 = make_float4(0.f, 0.f, 0.f, 0.f);
    for (int i = tid; i < 512; i += 256) {
        int idx = nbase0 * 8 + i;
        if (idx < N_NODES * 8) { g_agg1P[idx] = z4; g_agg1N[idx] = z4; }
    }
    if (tid < 64) {
        int n = nbase0 + tid;
        if (n < N_NODES) { g_cntP[n] = 0.f; g_cntN[n] = 0.f; }
    }
    __syncthreads();

    int jg = tid & 15, ng = tid >> 4;
    int branch = jg >> 3, jb = jg & 7;
    int nbase = nbase0 + ng * 4;
    int nidx[4];
    #pragma unroll
    for (int ni = 0; ni < 4; ni++) {
        int n = nbase + ni; if (n > N_NODES - 1) n = N_NODES - 1;
        nidx[ni] = n;
    }

    float acc[4][4];
    #pragma unroll
    for (int ni = 0; ni < 4; ni++)
        #pragma unroll
        for (int o = 0; o < 4; o++) acc[ni][o] = 0.f;

    #pragma unroll 4
    for (int ch = 0; ch < 16; ch++) {
        float4 v[4], w[4];
        #pragma unroll
        for (int ni = 0; ni < 4; ni++)
            v[ni] = __ldg((const float4*)(x + nidx[ni] * 64 + ch * 4));
        #pragma unroll
        for (int o = 0; o < 4; o++)
            w[o] = *(const float4*)&sW[branch][jb + 8 * o][ch * 4];
        #pragma unroll
        for (int ni = 0; ni < 4; ni++)
            #pragma unroll
            for (int o = 0; o < 4; o++) {
                acc[ni][o] = fmaf(v[ni].x, w[o].x, acc[ni][o]);
                acc[ni][o] = fmaf(v[ni].y, w[o].y, acc[ni][o]);
                acc[ni][o] = fmaf(v[ni].z, w[o].z, acc[ni][o]);
                acc[ni][o] = fmaf(v[ni].w, w[o].w, acc[ni][o]);
            }
    }

    #pragma unroll
    for (int ni = 0; ni < 4; ni++) {
        int n = nbase + ni;
        if (n < N_NODES) {
            #pragma unroll
            for (int o = 0; o < 4; o++)
                g_xT[n * 64 + branch * 32 + jb + 8 * o] = __float2half_rn(acc[ni][o]);
        }
    }
}

// ---------------- linear1: z = tanh(agg1*inv + x@Wself + b) ----------------
__global__ void __launch_bounds__(256, 4)
linear1_lite(const float* __restrict__ x,
             const float* __restrict__ w1b, const float* __restrict__ b1b,
             const float* __restrict__ w1u, const float* __restrict__ b1u)
{
    __shared__ float sW[2][32][KS1];   // self rows 64:127
    __shared__ float sB[64];
    int tid = threadIdx.x;
    for (int i = tid; i < 64 * 32; i += 256) {
        int k = i >> 5, j = i & 31;
        sW[0][j][k] = w1b[2048 + i];
        sW[1][j][k] = w1u[2048 + i];
    }
    if (tid < 32) { sB[tid] = b1b[tid]; sB[tid + 32] = b1u[tid]; }
    __syncthreads();

    int jg = tid & 15, ng = tid >> 4;
    int branch = jg >> 3, jb = jg & 7;
    int nbase = blockIdx.x * 64 + ng * 4;
    int nidx[4];
    #pragma unroll
    for (int ni = 0; ni < 4; ni++) {
        int n = nbase + ni; if (n > N_NODES - 1) n = N_NODES - 1;
        nidx[ni] = n;
    }

    float acc[4][4];
    #pragma unroll
    for (int ni = 0; ni < 4; ni++)
        #pragma unroll
        for (int o = 0; o < 4; o++)
            acc[ni][o] = sB[branch * 32 + jb + 8 * o];

    #pragma unroll 4
    for (int ch = 0; ch < 16; ch++) {
        float4 v[4], w[4];
        #pragma unroll
        for (int ni = 0; ni < 4; ni++)
            v[ni] = __ldg((const float4*)(x + nidx[ni] * 64 + ch * 4));
        #pragma unroll
        for (int o = 0; o < 4; o++)
            w[o] = *(const float4*)&sW[branch][jb + 8 * o][ch * 4];
        #pragma unroll
        for (int ni = 0; ni < 4; ni++)
            #pragma unroll
            for (int o = 0; o < 4; o++) {
                acc[ni][o] = fmaf(v[ni].x, w[o].x, acc[ni][o]);
                acc[ni][o] = fmaf(v[ni].y, w[o].y, acc[ni][o]);
                acc[ni][o] = fmaf(v[ni].z, w[o].z, acc[ni][o]);
                acc[ni][o] = fmaf(v[ni].w, w[o].w, acc[ni][o]);
            }
    }

    const float* agg = branch ? (const float*)g_agg1N : (const float*)g_agg1P;
    const float* cnt = branch ? g_cntN : g_cntP;
    float* zout = (float*)g_z;
    #pragma unroll
    for (int ni = 0; ni < 4; ni++) {
        int n = nbase + ni;
        if (n < N_NODES) {
            float inv = 1.0f / fmaxf(cnt[n], 1.0f);
            #pragma unroll
            for (int o = 0; o < 4; o++) {
                float a = __ldg(agg + n * 32 + jb + 8 * o);
                zout[n * 64 + branch * 32 + jb + 8 * o] = ftanh(acc[ni][o] + a * inv);
            }
        }
    }
}

// ---------------- transform2: zT = [u | v] (fp16 out) + zero agg2 ----------------
// u[0:32]=zp@w2b[0:32]   u[32:64]=zn@w2u[0:32]
// v[0:32]=zn@w2b[32:64]  v[32:64]=zp@w2u[32:64]
__global__ void __launch_bounds__(256, 4)
transform2_kernel(const float* __restrict__ w2b, const float* __restrict__ w2u)
{
    __shared__ float sW[2][32][KS1];   // w2b/w2u rows 0:64
    int tid = threadIdx.x;
    for (int i = tid; i < 64 * 32; i += 256) {
        int k = i >> 5, j = i & 31;
        sW[0][j][k] = w2b[i];
        sW[1][j][k] = w2u[i];
    }

    // zero this block's agg2 rows (32 nodes x 16 float4 per buffer)
    int nbase0 = blockIdx.x * 32;
    float4 z4 = make_float4(0.f, 0.f, 0.f, 0.f);
    for (int i = tid; i < 512; i += 256) {
        int idx = nbase0 * 16 + i;
        if (idx < N_NODES * 16) { g_agg2P[idx] = z4; g_agg2N[idx] = z4; }
    }
    __syncthreads();

    int jg = tid & 31, ng = tid >> 5;
    int q = jg >> 3, jb = jg & 7;
    int h  = (q == 1 || q == 2) ? 1 : 0;
    int wb = (q == 0 || q == 2) ? 0 : 1;
    int ro = (q >= 2) ? 32 : 0;
    int nbase = nbase0 + ng * 4;
    int nidx[4];
    #pragma unroll
    for (int ni = 0; ni < 4; ni++) {
        int n = nbase + ni; if (n > N_NODES - 1) n = N_NODES - 1;
        nidx[ni] = n;
    }

    const float* z = (const float*)g_z;
    float acc[4][4];
    #pragma unroll
    for (int ni = 0; ni < 4; ni++)
        #pragma unroll
        for (int o = 0; o < 4; o++) acc[ni][o] = 0.f;

    #pragma unroll
    for (int ch = 0; ch < 8; ch++) {
        float4 v[4], w[4];
        #pragma unroll
        for (int ni = 0; ni < 4; ni++)
            v[ni] = __ldg((const float4*)(z + nidx[ni] * 64 + h * 32 + ch * 4));
        #pragma unroll
        for (int o = 0; o < 4; o++)
            w[o] = *(const float4*)&sW[wb][jb + 8 * o][ro + ch * 4];
        #pragma unroll
        for (int ni = 0; ni < 4; ni++)
            #pragma unroll
            for (int o = 0; o < 4; o++) {
                acc[ni][o] = fmaf(v[ni].x, w[o].x, acc[ni][o]);
                acc[ni][o] = fmaf(v[ni].y, w[o].y, acc[ni][o]);
                acc[ni][o] = fmaf(v[ni].z, w[o].z, acc[ni][o]);
                acc[ni][o] = fmaf(v[ni].w, w[o].w, acc[ni][o]);
            }
    }

    #pragma unroll
    for (int ni = 0; ni < 4; ni++) {
        int n = nbase + ni;
        if (n < N_NODES) {
            #pragma unroll
            for (int o = 0; o < 4; o++)
                g_zT[n * 128 + q * 32 + jb + 8 * o] = __float2half_rn(acc[ni][o]);
        }
    }
}

// ---------------- linear2: out = tanh(agg2P*invP + agg2N*invN + z_self@Wself + b) ----------------
#define KS2 36
__global__ void __launch_bounds__(256, 4)
linear2_lite(const float* __restrict__ w2b, const float* __restrict__ b2b,
             const float* __restrict__ w2u, const float* __restrict__ b2u,
             float* __restrict__ out)
{
    __shared__ float sW[2][32][KS2];   // self rows 64:95
    __shared__ float sB[64];
    int tid = threadIdx.x;
    for (int i = tid; i < 32 * 32; i += 256) {
        int k = i >> 5, j = i & 31;
        sW[0][j][k] = w2b[2048 + i];
        sW[1][j][k] = w2u[2048 + i];
    }
    if (tid < 32) { sB[tid] = b2b[tid]; sB[tid + 32] = b2u[tid]; }
    __syncthreads();

    int jg = tid & 15, ng = tid >> 4;
    int branch = jg >> 3, jb = jg & 7;
    int nbase = blockIdx.x * 64 + ng * 4;
    int nidx[4];
    #pragma unroll
    for (int ni = 0; ni < 4; ni++) {
        int n = nbase + ni; if (n > N_NODES - 1) n = N_NODES - 1;
        nidx[ni] = n;
    }

    const float* z = (const float*)g_z;
    float acc[4][4];
    #pragma unroll
    for (int ni = 0; ni < 4; ni++)
        #pragma unroll
        for (int o = 0; o < 4; o++)
            acc[ni][o] = sB[branch * 32 + jb + 8 * o];

    #pragma unroll
    for (int ch = 0; ch < 8; ch++) {
        float4 v[4], w[4];
        #pragma unroll
        for (int ni = 0; ni < 4; ni++)
            v[ni] = __ldg((const float4*)(z + nidx[ni] * 64 + branch * 32 + ch * 4));
        #pragma unroll
        for (int o = 0; o < 4; o++)
            w[o] = *(const float4*)&sW[branch][jb + 8 * o][ch * 4];
        #pragma unroll
        for (int ni = 0; ni < 4; ni++)
            #pragma unroll
            for (int o = 0; o < 4; o++) {
                acc[ni][o] = fmaf(v[ni].x, w[o].x, acc[ni][o]);
                acc[ni][o] = fmaf(v[ni].y, w[o].y, acc[ni][o]);
                acc[ni][o] = fmaf(v[ni].z, w[o].z, acc[ni][o]);
                acc[ni][o] = fmaf(v[ni].w, w[o].w, acc[ni][o]);
            }
    }

    const float* aU = (const float*)g_agg2P;
    const float* aV = (const float*)g_agg2N;
    #pragma unroll
    for (int ni = 0; ni < 4; ni++) {
        int n = nbase + ni;
        if (n < N_NODES) {
            float invP = 1.0f / fmaxf(g_cntP[n], 1.0f);
            float invN = 1.0f / fmaxf(g_cntN[n], 1.0f);
            #pragma unroll
            for (int o = 0; o < 4; o++) {
                int j = branch * 32 + jb + 8 * o;
                float au = __ldg(aU + n * 64 + j);
                float av = __ldg(aV + n * 64 + j);
                out[n * 64 + j] = ftanh(acc[ni][o] + au * invP + av * invN);
            }
        }
    }
}

// ---------------- launch ----------------
extern "C" void kernel_launch(void* const* d_in, const int* in_sizes, int n_in,
                              void* d_out, int out_size)
{
    const float* x    = (const float*)d_in[0];
    const int* posEI  = (const int*)d_in[1];
    const int* negEI  = (const int*)d_in[2];
    const float* w1b  = (const float*)d_in[3];
    const float* b1b  = (const float*)d_in[4];
    const float* w1u  = (const float*)d_in[5];
    const float* b1u  = (const float*)d_in[6];
    const float* w2b  = (const float*)d_in[7];
    const float* b2b  = (const float*)d_in[8];
    const float* w2u  = (const float*)d_in[9];
    const float* b2u  = (const float*)d_in[10];
    float* out = (float*)d_out;

    int E = in_sizes[1] / 2;             // 1,600,000
    const int* posSrc = posEI;
    const int* posDst = posEI + E;
    const int* negSrc = negEI;
    const int* negDst = negEI + E;

    int agg1Grid  = (E * 16 + 255) / 256;   // 100,000 (pos+neg merged)
    int agg2Grid  = (E * 32 + 255) / 256;   // 200,000 (pos+neg merged)
    int lin64Grid = (N_NODES + 63) / 64;    // 1563
    int lin32Grid = (N_NODES + 31) / 32;    // 3125

    // --- layer 1 ---
    transform1_kernel<<<lin64Grid, 256>>>(x, w1b, w1u);
    agg1_kernel<<<agg1Grid, 256>>>(posSrc, posDst, negSrc, negDst, E);
    linear1_lite<<<lin64Grid, 256>>>(x, w1b, b1b, w1u, b1u);

    // --- layer 2 ---
    transform2_kernel<<<lin32Grid, 256>>>(w2b, w2u);
    agg2_kernel<<<agg2Grid, 256>>>(posSrc, posDst, negSrc, negDst, E);
    linear2_lite<<<lin64Grid, 256>>>(w2b, b2b, w2u, b2u, out);
}